// round 2
// baseline (speedup 1.0000x reference)
#include <cuda_runtime.h>
#include <mma.h>
#include <cstdint>

using namespace nvcuda;

#define Bn  4
#define Ln  1024
#define Dn  768
#define Hn  6
#define DHn 128
#define BHn (Bn*Hn)
#define EPSf 1e-5f
#define GLD 132   /* smem leading dim: 128 + 4 pad */

#define OFF_CO 0
#define OFF_W  (BHn*Ln*Ln)          /* 25165824 */
#define OFF_V  (OFF_W + Bn*Ln)      /* 25169920 */

// ---------------- scratch (static device arrays; allocation-free) ----------------
__device__ float  g_q2[BHn*Ln];
__device__ float  g_k2[BHn*Ln];
__device__ float  g_G[BHn*DHn*DHn];         // per-bh Gram K^T K (24 x 16384)
__device__ double g_T[BHn];                 // per-bh  sum of (q.k)^2
__device__ double g_sum1[Hn];
__device__ double g_sumsq1[Hn];
__device__ float  g_scale1[Hn];
__device__ float  g_shift1[Hn];
__device__ float  g_rowsum[BHn*Ln];         // softmax denominators
__device__ float  g_w[BHn*Ln];              // column sums (B,H,L)
__device__ float  g_scale2[Hn];
__device__ float  g_shift2[Hn];
__device__ float  g_p[Bn*Ln];
__device__ unsigned char g_valid[Bn*Ln];

// ---------------- zero accumulators (graph replays must be idempotent) ----------------
__global__ void zero_kernel() {
    int idx = blockIdx.x*blockDim.x + threadIdx.x;
    if (idx < BHn*DHn*DHn) g_G[idx] = 0.f;
    if (idx < BHn*Ln) { g_w[idx] = 0.f; g_rowsum[idx] = 0.f; }
    if (idx < BHn) g_T[idx] = 0.0;
    if (idx < Hn) { g_sum1[idx] = 0.0; g_sumsq1[idx] = 0.0; }
}

// ---------------- mask: derive valid[] from bx_packed with dtype sniff ----------------
__global__ void mask_kernel(const unsigned int* w) {
    __shared__ int s_float, s_byte;
    if (threadIdx.x == 0) { s_float = 0; s_byte = 0; }
    __syncthreads();
    for (int i = threadIdx.x; i < (Bn*Ln)/4; i += blockDim.x) {
        unsigned v = w[i];
        if (v == 0x3f800000u) atomicOr(&s_float, 1);
        else if (v > 1u)      atomicOr(&s_byte, 1);
    }
    __syncthreads();
    int byte_mode = (!s_float) && s_byte;
    const unsigned char* bytes = (const unsigned char*)w;
    for (int i = threadIdx.x; i < Bn*Ln; i += blockDim.x) {
        bool padded = byte_mode ? (bytes[i] != 0) : (w[i] != 0u);
        g_valid[i] = padded ? 0 : 1;
    }
}

// ---------------- Vh output: transpose copy (B,L,H,DH) -> (B,H,L,DH) ----------------
__global__ void vout_kernel(const float* __restrict__ V, float* __restrict__ out) {
    int idx = blockIdx.x*blockDim.x + threadIdx.x;
    if (idx >= BHn*Ln*DHn/4) return;
    int d4 = idx & 31;
    int l  = (idx >> 5) & (Ln-1);
    int h  = (idx >> 15) % Hn;
    int b  = idx / (32*Ln*Hn);
    float4 v = *(const float4*)(V + ((size_t)(b*Ln + l))*Dn + h*DHn + d4*4);
    ((float4*)(out + OFF_V))[idx] = v;
}

// ---------------- A1: per (bh, j-chunk): k2 + Gram partial G += Kc^T Kc ----------------
__global__ void __launch_bounds__(256) gramK_kernel(const float* __restrict__ K) {
    extern __shared__ float sm[];
    float* Ks = sm;                 // 128 x GLD
    float* Cs = sm + 128*GLD;
    int bh = blockIdx.y; int b = bh / Hn, h = bh % Hn;
    int j0 = blockIdx.x*128;
    const float* Kb = K + (size_t)b*Ln*Dn + h*DHn;

    for (int t = threadIdx.x; t < 128*32; t += 256) {
        int r = t >> 5, c = t & 31;
        float4 k = *(const float4*)(Kb + (size_t)(j0 + r)*Dn + c*4);
        *(float4*)&Ks[r*GLD + c*4] = k;
    }
    __syncthreads();
    // exact k2 from raw values (2 threads per row)
    {
        int r = threadIdx.x >> 1, half = (threadIdx.x & 1)*64;
        float s = 0.f;
        #pragma unroll 8
        for (int c = 0; c < 64; c++) { float x = Ks[r*GLD + half + c]; s += x*x; }
        s += __shfl_xor_sync(0xffffffffu, s, 1);
        if ((threadIdx.x & 1) == 0) g_k2[bh*Ln + j0 + r] = s;
    }
    __syncthreads();
    // convert in place to tf32
    for (int t = threadIdx.x; t < 128*128; t += 256) {
        int r = t >> 7, c = t & 127;
        Ks[r*GLD + c] = wmma::__float_to_tf32(Ks[r*GLD + c]);
    }
    __syncthreads();

    int warp = threadIdx.x >> 5;
    int ar = warp & 3, bc = warp >> 2;
    wmma::fragment<wmma::accumulator, 16,16,8, float> acc[2][4];
    #pragma unroll
    for (int m = 0; m < 2; m++)
        #pragma unroll
        for (int n = 0; n < 4; n++) wmma::fill_fragment(acc[m][n], 0.f);
    #pragma unroll
    for (int j = 0; j < 128; j += 8) {
        wmma::fragment<wmma::matrix_a, 16,16,8, wmma::precision::tf32, wmma::col_major> af[2];
        wmma::fragment<wmma::matrix_b, 16,16,8, wmma::precision::tf32, wmma::row_major> bf[4];
        #pragma unroll
        for (int m = 0; m < 2; m++)
            wmma::load_matrix_sync(af[m], Ks + j*GLD + ar*32 + m*16, GLD);
        #pragma unroll
        for (int n = 0; n < 4; n++)
            wmma::load_matrix_sync(bf[n], Ks + j*GLD + bc*64 + n*16, GLD);
        #pragma unroll
        for (int m = 0; m < 2; m++)
            #pragma unroll
            for (int n = 0; n < 4; n++)
                wmma::mma_sync(acc[m][n], af[m], bf[n], acc[m][n]);
    }
    __syncthreads();
    #pragma unroll
    for (int m = 0; m < 2; m++)
        #pragma unroll
        for (int n = 0; n < 4; n++)
            wmma::store_matrix_sync(Cs + (ar*32 + m*16)*GLD + bc*64 + n*16, acc[m][n], GLD,
                                    wmma::mem_row_major);
    __syncthreads();
    float* Gp = g_G + bh*DHn*DHn;
    for (int t = threadIdx.x; t < 128*128; t += 256) {
        int r = t >> 7, c = t & 127;
        atomicAdd(&Gp[t], Cs[r*GLD + c]);
    }
}

// ---------------- A2: per (bh, i-chunk): q2 + T += sum( (Qc G) o Qc ) ----------------
__global__ void __launch_bounds__(256) yq_kernel(const float* __restrict__ Q) {
    extern __shared__ float sm[];
    float* Qs = sm;
    float* Gs = sm + 128*GLD;
    float* Cs = sm + 2*128*GLD;
    int bh = blockIdx.y; int b = bh / Hn, h = bh % Hn;
    int i0 = blockIdx.x*128;
    const float* Qb = Q + (size_t)b*Ln*Dn + h*DHn;
    const float* Gp = g_G + bh*DHn*DHn;

    for (int t = threadIdx.x; t < 128*32; t += 256) {
        int r = t >> 5, c = t & 31;
        float4 q = *(const float4*)(Qb + (size_t)(i0 + r)*Dn + c*4);
        *(float4*)&Qs[r*GLD + c*4] = q;
        float4 g = *(const float4*)(Gp + t*4);
        Gs[r*GLD + c*4 + 0] = wmma::__float_to_tf32(g.x);
        Gs[r*GLD + c*4 + 1] = wmma::__float_to_tf32(g.y);
        Gs[r*GLD + c*4 + 2] = wmma::__float_to_tf32(g.z);
        Gs[r*GLD + c*4 + 3] = wmma::__float_to_tf32(g.w);
    }
    __syncthreads();
    {
        int r = threadIdx.x >> 1, half = (threadIdx.x & 1)*64;
        float s = 0.f;
        #pragma unroll 8
        for (int c = 0; c < 64; c++) { float x = Qs[r*GLD + half + c]; s += x*x; }
        s += __shfl_xor_sync(0xffffffffu, s, 1);
        if ((threadIdx.x & 1) == 0) g_q2[bh*Ln + i0 + r] = s;
    }
    __syncthreads();
    for (int t = threadIdx.x; t < 128*128; t += 256) {
        int r = t >> 7, c = t & 127;
        Qs[r*GLD + c] = wmma::__float_to_tf32(Qs[r*GLD + c]);
    }
    __syncthreads();

    int warp = threadIdx.x >> 5;
    int ar = warp & 3, bc = warp >> 2;
    wmma::fragment<wmma::accumulator, 16,16,8, float> acc[2][4];
    #pragma unroll
    for (int m = 0; m < 2; m++)
        #pragma unroll
        for (int n = 0; n < 4; n++) wmma::fill_fragment(acc[m][n], 0.f);
    #pragma unroll
    for (int k = 0; k < 128; k += 8) {
        wmma::fragment<wmma::matrix_a, 16,16,8, wmma::precision::tf32, wmma::row_major> af[2];
        wmma::fragment<wmma::matrix_b, 16,16,8, wmma::precision::tf32, wmma::row_major> bf[4];
        #pragma unroll
        for (int m = 0; m < 2; m++)
            wmma::load_matrix_sync(af[m], Qs + (ar*32 + m*16)*GLD + k, GLD);
        #pragma unroll
        for (int n = 0; n < 4; n++)
            wmma::load_matrix_sync(bf[n], Gs + k*GLD + bc*64 + n*16, GLD);
        #pragma unroll
        for (int m = 0; m < 2; m++)
            #pragma unroll
            for (int n = 0; n < 4; n++)
                wmma::mma_sync(acc[m][n], af[m], bf[n], acc[m][n]);
    }
    __syncthreads();
    #pragma unroll
    for (int m = 0; m < 2; m++)
        #pragma unroll
        for (int n = 0; n < 4; n++)
            wmma::store_matrix_sync(Cs + (ar*32 + m*16)*GLD + bc*64 + n*16, acc[m][n], GLD,
                                    wmma::mem_row_major);
    __syncthreads();
    float ts = 0.f;
    for (int t = threadIdx.x; t < 128*128; t += 256) {
        int r = t >> 7, c = t & 127;
        ts += Cs[r*GLD + c]*Qs[r*GLD + c];
    }
    double d = (double)ts;
    #pragma unroll
    for (int o = 16; o; o >>= 1) d += __shfl_xor_sync(0xffffffffu, d, o);
    __shared__ double rd[8];
    int lane = threadIdx.x & 31;
    if (lane == 0) rd[warp] = d;
    __syncthreads();
    if (threadIdx.x == 0) {
        double s = 0.0;
        for (int i = 0; i < 8; i++) s += rd[i];
        atomicAdd(&g_T[bh], s);
    }
}

// ---------------- finalize BN1 sums per bh -> per-head accumulators ----------------
__global__ void __launch_bounds__(128) finalize1_kernel(const float* __restrict__ Q,
                                                        const float* __restrict__ K) {
    int bh = blockIdx.x; int b = bh / Hn, h = bh % Hn;
    int d = threadIdx.x;
    const float* Qb = Q + (size_t)b*Ln*Dn + h*DHn;
    const float* Kb = K + (size_t)b*Ln*Dn + h*DHn;
    float u = 0.f, P = 0.f, v = 0.f, R = 0.f;
    #pragma unroll 4
    for (int i = 0; i < Ln; i++) {
        float q = Qb[(size_t)i*Dn + d], q2 = g_q2[bh*Ln + i];
        float k = Kb[(size_t)i*Dn + d], k2 = g_k2[bh*Ln + i];
        u += q; P += q2*q; v += k; R += k2*k;
    }
    __shared__ float su[128], sv[128], sP[128], sR[128];
    su[d] = u; sv[d] = v; sP[d] = P; sR[d] = R;
    float a = 0.f, a2 = 0.f, bb = 0.f, b2 = 0.f;
    for (int i = d; i < Ln; i += 128) {
        float x = g_q2[bh*Ln + i]; a += x; a2 += x*x;
        float y = g_k2[bh*Ln + i]; bb += y; b2 += y*y;
    }
    __syncthreads();
    float uv = su[d]*sv[d], Pv = sP[d]*sv[d], Ru = sR[d]*su[d];
    // block reduce 7 scalars in double
    double val[7] = {(double)uv, (double)Pv, (double)Ru, (double)a, (double)a2, (double)bb, (double)b2};
    __shared__ double red[7][4];
    int warp = d >> 5, lane = d & 31;
    #pragma unroll
    for (int t = 0; t < 7; t++) {
        double x = val[t];
        #pragma unroll
        for (int o = 16; o; o >>= 1) x += __shfl_xor_sync(0xffffffffu, x, o);
        if (lane == 0) red[t][warp] = x;
    }
    __syncthreads();
    if (d == 0) {
        double UV = 0, PV = 0, RU = 0, A = 0, A2 = 0, B = 0, B2 = 0;
        for (int wgi = 0; wgi < 4; wgi++) {
            UV += red[0][wgi]; PV += red[1][wgi]; RU += red[2][wgi];
            A  += red[3][wgi]; A2 += red[4][wgi]; B  += red[5][wgi]; B2 += red[6][wgi];
        }
        double sum_s = -((double)Ln*A + (double)Ln*B - 2.0*UV);
        double SS = (double)Ln*A2 + (double)Ln*B2 + 2.0*A*B - 4.0*(PV + RU) + 4.0*g_T[bh];
        atomicAdd(&g_sum1[h], sum_s);
        atomicAdd(&g_sumsq1[h], SS);
    }
}

// ---------------- BN1 stats finalize ----------------
__global__ void stats1_kernel(const float* __restrict__ g1, const float* __restrict__ b1) {
    int h = threadIdx.x;
    if (h < Hn) {
        double n = (double)Bn*Ln*Ln;
        double m = g_sum1[h]/n;
        double var = g_sumsq1[h]/n - m*m;
        float rstd = (float)rsqrt(var + (double)EPSf);
        g_scale1[h] = g1[h]*rstd;
        g_shift1[h] = b1[h] - (float)m*rstd*g1[h];
    }
}

// ---------------- main GEMM: co = exp(BN1(scores) masked), rowsum accumulate ----------------
__global__ void __launch_bounds__(256) gemm_kernel(const float* __restrict__ Q,
                                                   const float* __restrict__ K,
                                                   float* __restrict__ co) {
    extern __shared__ float sm[];
    float* Qs = sm;                  // 128 x GLD
    float* Ks = sm + 128*GLD;
    float* Cs = sm;                  // alias Qs after mma loop
    __shared__ float k2s[128], q2s[128], rowsumsh[128];
    __shared__ unsigned char vr[128], vc[128];

    int bh = blockIdx.z; int b = bh / Hn, h = bh % Hn;
    int bi0 = blockIdx.y*128, bj0 = blockIdx.x*128;
    const float* Qb = Q + (size_t)b*Ln*Dn + h*DHn;
    const float* Kb = K + (size_t)b*Ln*Dn + h*DHn;

    if (threadIdx.x < 128) {
        int t = threadIdx.x;
        k2s[t] = g_k2[bh*Ln + bj0 + t];
        q2s[t] = g_q2[bh*Ln + bi0 + t];
        vc[t]  = g_valid[b*Ln + bj0 + t];
        vr[t]  = g_valid[b*Ln + bi0 + t];
    }
    for (int t = threadIdx.x; t < 128*32; t += 256) {
        int r = t >> 5, c = t & 31;
        float4 q = *(const float4*)(Qb + (size_t)(bi0 + r)*Dn + c*4);
        float4 k = *(const float4*)(Kb + (size_t)(bj0 + r)*Dn + c*4);
        Qs[r*GLD + c*4 + 0] = wmma::__float_to_tf32(q.x);
        Qs[r*GLD + c*4 + 1] = wmma::__float_to_tf32(q.y);
        Qs[r*GLD + c*4 + 2] = wmma::__float_to_tf32(q.z);
        Qs[r*GLD + c*4 + 3] = wmma::__float_to_tf32(q.w);
        Ks[r*GLD + c*4 + 0] = wmma::__float_to_tf32(k.x);
        Ks[r*GLD + c*4 + 1] = wmma::__float_to_tf32(k.y);
        Ks[r*GLD + c*4 + 2] = wmma::__float_to_tf32(k.z);
        Ks[r*GLD + c*4 + 3] = wmma::__float_to_tf32(k.w);
    }
    __syncthreads();

    int warp = threadIdx.x >> 5, lane = threadIdx.x & 31;
    int wr = warp & 3, wc = warp >> 2;
    wmma::fragment<wmma::accumulator, 16,16,8, float> acc[2][4];
    #pragma unroll
    for (int m = 0; m < 2; m++)
        #pragma unroll
        for (int n = 0; n < 4; n++) wmma::fill_fragment(acc[m][n], 0.f);
    #pragma unroll
    for (int k = 0; k < 128; k += 8) {
        wmma::fragment<wmma::matrix_a, 16,16,8, wmma::precision::tf32, wmma::row_major> af[2];
        wmma::fragment<wmma::matrix_b, 16,16,8, wmma::precision::tf32, wmma::col_major> bf[4];
        #pragma unroll
        for (int m = 0; m < 2; m++)
            wmma::load_matrix_sync(af[m], Qs + (wr*32 + m*16)*GLD + k, GLD);
        #pragma unroll
        for (int n = 0; n < 4; n++)
            wmma::load_matrix_sync(bf[n], Ks + (wc*64 + n*16)*GLD + k, GLD);
        #pragma unroll
        for (int m = 0; m < 2; m++)
            #pragma unroll
            for (int n = 0; n < 4; n++)
                wmma::mma_sync(acc[m][n], af[m], bf[n], acc[m][n]);
    }
    __syncthreads();
    #pragma unroll
    for (int m = 0; m < 2; m++)
        #pragma unroll
        for (int n = 0; n < 4; n++)
            wmma::store_matrix_sync(Cs + (wr*32 + m*16)*GLD + wc*64 + n*16, acc[m][n], GLD,
                                    wmma::mem_row_major);
    __syncthreads();

    float scale = g_scale1[h], shift = g_shift1[h];
    #pragma unroll
    for (int it = 0; it < 16; it++) {
        int row = warp + it*8;
        float4 c4 = *(const float4*)&Cs[row*GLD + lane*4];
        float q2v = q2s[row];
        bool rv = vr[row] != 0;
        int j = lane*4;
        float z0 = (rv && vc[j+0]) ? (2.f*c4.x - q2v - k2s[j+0])*scale + shift : 0.f;
        float z1 = (rv && vc[j+1]) ? (2.f*c4.y - q2v - k2s[j+1])*scale + shift : 0.f;
        float z2 = (rv && vc[j+2]) ? (2.f*c4.z - q2v - k2s[j+2])*scale + shift : 0.f;
        float z3 = (rv && vc[j+3]) ? (2.f*c4.w - q2v - k2s[j+3])*scale + shift : 0.f;
        float4 e;
        e.x = __expf(z0); e.y = __expf(z1); e.z = __expf(z2); e.w = __expf(z3);
        float rs = e.x + e.y + e.z + e.w;
        #pragma unroll
        for (int o = 16; o; o >>= 1) rs += __shfl_xor_sync(0xffffffffu, rs, o);
        if (lane == 0) rowsumsh[row] = rs;
        *(float4*)(co + ((size_t)(bh*Ln + bi0 + row))*Ln + bj0 + j) = e;
    }
    __syncthreads();
    if (threadIdx.x < 128)
        atomicAdd(&g_rowsum[bh*Ln + bi0 + threadIdx.x], rowsumsh[threadIdx.x]);
}

// ---------------- divide by rowsum in place + column sums ----------------
__global__ void __launch_bounds__(256) divide_kernel(float* __restrict__ co) {
    int bh = blockIdx.x >> 3;
    int r0 = (blockIdx.x & 7)*128;
    __shared__ float inv[128];
    if (threadIdx.x < 128) inv[threadIdx.x] = 1.f / g_rowsum[bh*Ln + r0 + threadIdx.x];
    __syncthreads();
    float4* p = (float4*)(co + ((size_t)bh*Ln + r0)*Ln);
    float c0 = 0.f, c1 = 0.f, c2 = 0.f, c3 = 0.f;
    #pragma unroll 4
    for (int it = 0; it < 128; it++) {
        int idx4 = threadIdx.x + it*256;
        float4 x = p[idx4];
        float s = inv[it >> 1];  // row = idx4>>8 ; 256 float4/row, 256 threads -> 2 iters/row
        // careful: idx4>>8 == (threadIdx.x + it*256)>>8 ; with tid<256: row = it>>1 only if 512 f4/row
        // Ln=1024 floats = 256 float4 per row -> row = it. fix:
        s = inv[(idx4 >> 8)];
        x.x *= s; x.y *= s; x.z *= s; x.w *= s;
        p[idx4] = x;
        c0 += x.x; c1 += x.y; c2 += x.z; c3 += x.w;
    }
    int j = threadIdx.x*4;
    atomicAdd(&g_w[bh*Ln + j + 0], c0);
    atomicAdd(&g_w[bh*Ln + j + 1], c1);
    atomicAdd(&g_w[bh*Ln + j + 2], c2);
    atomicAdd(&g_w[bh*Ln + j + 3], c3);
}

// ---------------- BN2 stats (per head over B*L) ----------------
__global__ void stats2_kernel(const float* __restrict__ g2, const float* __restrict__ b2) {
    int h = blockIdx.x;
    int tid = threadIdx.x;
    float ls = 0.f, lq = 0.f;
    for (int b = 0; b < Bn; b++) {
        const float* wp = g_w + (b*Hn + h)*Ln;
        for (int j = tid; j < Ln; j += 256) { float x = wp[j]; ls += x; lq += x*x; }
    }
    double ds = (double)ls, dq = (double)lq;
    #pragma unroll
    for (int o = 16; o; o >>= 1) {
        ds += __shfl_xor_sync(0xffffffffu, ds, o);
        dq += __shfl_xor_sync(0xffffffffu, dq, o);
    }
    __shared__ double rs[8], rq[8];
    int warp = tid >> 5, lane = tid & 31;
    if (lane == 0) { rs[warp] = ds; rq[warp] = dq; }
    __syncthreads();
    if (tid == 0) {
        double S = 0.0, Q2 = 0.0;
        for (int wgi = 0; wgi < 8; wgi++) { S += rs[wgi]; Q2 += rq[wgi]; }
        double n = (double)Bn*Ln;
        double m = S/n;
        double var = Q2/n - m*m;
        float rstd = (float)rsqrt(var + (double)EPSf);
        g_scale2[h] = g2[h]*rstd;
        g_shift2[h] = b2[h] - (float)m*rstd*g2[h];
    }
}

// ---------------- posterior gate ----------------
__global__ void gate_kernel(const float* __restrict__ Wp, const float* __restrict__ bp) {
    int idx = blockIdx.x*blockDim.x + threadIdx.x;
    if (idx >= Bn*Ln) return;
    int b = idx >> 10, l = idx & (Ln-1);
    float z0 = bp[0], z1 = bp[1];
    #pragma unroll
    for (int h = 0; h < Hn; h++) {
        float wn = g_w[(b*Hn + h)*Ln + l]*g_scale2[h] + g_shift2[h];
        z0 += Wp[h]      * wn;
        z1 += Wp[Hn + h] * wn;
    }
    float d = z1 - z0;
    g_p[idx] = 1.f/(1.f + __expf(d));
}

// ---------------- final masked softmax over L per batch ----------------
__global__ void final_kernel(float* __restrict__ out) {
    int b = blockIdx.x, l = threadIdx.x;
    __shared__ float redm[32], redsum[32], bc[2];
    const float NEG_INF = __int_as_float(0xff800000);
    float x = g_valid[b*Ln + l] ? g_p[b*Ln + l] : NEG_INF;
    int warp = l >> 5, lane = l & 31;
    float m = x;
    #pragma unroll
    for (int o = 16; o; o >>= 1) m = fmaxf(m, __shfl_xor_sync(0xffffffffu, m, o));
    if (lane == 0) redm[warp] = m;
    __syncthreads();
    if (warp == 0) {
        m = redm[lane];
        #pragma unroll
        for (int o = 16; o; o >>= 1) m = fmaxf(m, __shfl_xor_sync(0xffffffffu, m, o));
        if (lane == 0) bc[0] = m;
    }
    __syncthreads();
    m = bc[0];
    float e = __expf(x - m);
    float s = e;
    #pragma unroll
    for (int o = 16; o; o >>= 1) s += __shfl_xor_sync(0xffffffffu, s, o);
    if (lane == 0) redsum[warp] = s;
    __syncthreads();
    if (warp == 0) {
        s = redsum[lane];
        #pragma unroll
        for (int o = 16; o; o >>= 1) s += __shfl_xor_sync(0xffffffffu, s, o);
        if (lane == 0) bc[1] = s;
    }
    __syncthreads();
    out[OFF_W + b*Ln + l] = e / bc[1];
}

// ---------------- launch ----------------
extern "C" void kernel_launch(void* const* d_in, const int* in_sizes, int n_in,
                              void* d_out, int out_size) {
    const float* Q  = (const float*)d_in[0];
    const float* K  = (const float*)d_in[1];
    const float* V  = (const float*)d_in[2];
    const unsigned int* bx = (const unsigned int*)d_in[4];
    const float* g1 = (const float*)d_in[5];
    const float* b1 = (const float*)d_in[6];
    const float* g2 = (const float*)d_in[7];
    const float* b2 = (const float*)d_in[8];
    const float* Wp = (const float*)d_in[9];
    const float* bp = (const float*)d_in[10];
    float* out = (float*)d_out;

    const int SM2 = 2*128*GLD*4;   // 135168
    const int SM3 = 3*128*GLD*4;   // 202752
    cudaFuncSetAttribute(gramK_kernel, cudaFuncAttributeMaxDynamicSharedMemorySize, SM2);
    cudaFuncSetAttribute(yq_kernel,    cudaFuncAttributeMaxDynamicSharedMemorySize, SM3);
    cudaFuncSetAttribute(gemm_kernel,  cudaFuncAttributeMaxDynamicSharedMemorySize, SM2);

    zero_kernel<<<(BHn*DHn*DHn + 255)/256, 256>>>();
    mask_kernel<<<1, 256>>>(bx);
    vout_kernel<<<(BHn*Ln*DHn/4 + 255)/256, 256>>>(V, out);
    gramK_kernel<<<dim3(8, BHn), 256, SM2>>>(K);
    yq_kernel<<<dim3(8, BHn), 256, SM3>>>(Q);
    finalize1_kernel<<<BHn, 128>>>(Q, K);
    stats1_kernel<<<1, 32>>>(g1, b1);
    gemm_kernel<<<dim3(8, 8, BHn), 256, SM2>>>(Q, K, out);
    divide_kernel<<<BHn*8, 256>>>(out);
    stats2_kernel<<<Hn, 256>>>(g2, b2);
    gate_kernel<<<(Bn*Ln + 255)/256, 256>>>(Wp, bp);
    final_kernel<<<Bn, Ln>>>(out);
}

// round 3
// speedup vs baseline: 2.1832x; 2.1832x over previous
#include <cuda_runtime.h>
#include <mma.h>
#include <cstdint>

using namespace nvcuda;

#define Bn  4
#define Ln  1024
#define Dn  768
#define Hn  6
#define DHn 128
#define BHn (Bn*Hn)
#define EPSf 1e-5f
#define GLD 132   /* smem leading dim: 128 + 4 pad */

#define OFF_CO 0
#define OFF_W  (BHn*Ln*Ln)          /* 25165824 */
#define OFF_V  (OFF_W + Bn*Ln)      /* 25169920 */

// ---------------- scratch (static device arrays; allocation-free) ----------------
__device__ double g_sum1[Hn];
__device__ double g_sumsq1[Hn];
__device__ float  g_scale1[Hn];
__device__ float  g_shift1[Hn];
__device__ float  g_w[BHn*Ln];              // column sums (B,H,L)
__device__ float  g_scale2[Hn];
__device__ float  g_shift2[Hn];
__device__ float  g_p[Bn*Ln];
__device__ unsigned char g_valid[Bn*Ln];

// ---------------- zero accumulators (graph replays must be idempotent) ----------------
__global__ void zero_kernel() {
    int idx = blockIdx.x*blockDim.x + threadIdx.x;
    if (idx < BHn*Ln) g_w[idx] = 0.f;
    if (idx < Hn) { g_sum1[idx] = 0.0; g_sumsq1[idx] = 0.0; }
}

// ---------------- mask: derive valid[] from bx_packed with dtype sniff ----------------
__global__ void mask_kernel(const unsigned int* w) {
    __shared__ int s_float, s_byte;
    if (threadIdx.x == 0) { s_float = 0; s_byte = 0; }
    __syncthreads();
    for (int i = threadIdx.x; i < (Bn*Ln)/4; i += blockDim.x) {
        unsigned v = w[i];
        if (v == 0x3f800000u) atomicOr(&s_float, 1);
        else if (v > 1u)      atomicOr(&s_byte, 1);
    }
    __syncthreads();
    int byte_mode = (!s_float) && s_byte;
    const unsigned char* bytes = (const unsigned char*)w;
    for (int i = threadIdx.x; i < Bn*Ln; i += blockDim.x) {
        bool padded = byte_mode ? (bytes[i] != 0) : (w[i] != 0u);
        g_valid[i] = padded ? 0 : 1;
    }
}

// ---------------- Vh output: transpose copy (B,L,H,DH) -> (B,H,L,DH) ----------------
__global__ void vout_kernel(const float* __restrict__ V, float* __restrict__ out) {
    int idx = blockIdx.x*blockDim.x + threadIdx.x;
    if (idx >= BHn*Ln*DHn/4) return;
    int d4 = idx & 31;
    int l  = (idx >> 5) & (Ln-1);
    int h  = (idx >> 15) % Hn;
    int b  = idx / (32*Ln*Hn);
    float4 v = *(const float4*)(V + ((size_t)(b*Ln + l))*Dn + h*DHn + d4*4);
    ((float4*)(out + OFF_V))[idx] = v;
}

// ---------------- main GEMM: raw scores S = 2QK^T - q2 - k2 -> co, + BN1 stats ----------------
// CTA tile 256x128, warp tile 64x64 (4x2 warp grid), K=128 full in smem (tf32).
__global__ void __launch_bounds__(256) gemm_kernel(const float* __restrict__ Q,
                                                   const float* __restrict__ K,
                                                   float* __restrict__ co) {
    extern __shared__ float sm[];
    float* As = sm;                  // 256 x GLD (tf32)
    float* Bs = sm + 256*GLD;        // 128 x GLD (tf32)
    float* Cs = sm;                  // alias As after mma loop (256 x GLD)
    __shared__ float q2s[256], k2s[128];
    __shared__ double rs[8], rq[8];

    int bh = blockIdx.z; int b = bh / Hn, h = bh % Hn;
    int bi0 = blockIdx.y*256, bj0 = blockIdx.x*128;
    const float* Qb = Q + (size_t)b*Ln*Dn + h*DHn;
    const float* Kb = K + (size_t)b*Ln*Dn + h*DHn;
    int tid = threadIdx.x, warp = tid >> 5, lane = tid & 31;

    // load A (256x128) + B (128x128), convert to tf32 in registers
    for (int t = tid; t < 256*32; t += 256) {
        int r = t >> 5, c = t & 31;
        float4 q = *(const float4*)(Qb + (size_t)(bi0 + r)*Dn + c*4);
        As[r*GLD + c*4 + 0] = wmma::__float_to_tf32(q.x);
        As[r*GLD + c*4 + 1] = wmma::__float_to_tf32(q.y);
        As[r*GLD + c*4 + 2] = wmma::__float_to_tf32(q.z);
        As[r*GLD + c*4 + 3] = wmma::__float_to_tf32(q.w);
    }
    for (int t = tid; t < 128*32; t += 256) {
        int r = t >> 5, c = t & 31;
        float4 k = *(const float4*)(Kb + (size_t)(bj0 + r)*Dn + c*4);
        Bs[r*GLD + c*4 + 0] = wmma::__float_to_tf32(k.x);
        Bs[r*GLD + c*4 + 1] = wmma::__float_to_tf32(k.y);
        Bs[r*GLD + c*4 + 2] = wmma::__float_to_tf32(k.z);
        Bs[r*GLD + c*4 + 3] = wmma::__float_to_tf32(k.w);
    }
    __syncthreads();

    // row norms from smem tf32: warp-per-row, float4 per lane
    #pragma unroll
    for (int it = 0; it < 4; it++) {            // 8 warps x 4 = 32 rows/warp over 256 A-rows... 256/8=32
        int row = warp*32 + it*8 + (lane >> 2); // 8 rows per it, 4 lanes per row
        float4 x = *(const float4*)&As[row*GLD + (lane & 3)*32 + 0];
        float4 y = *(const float4*)&As[row*GLD + (lane & 3)*32 + 4];
        float4 z = *(const float4*)&As[row*GLD + (lane & 3)*32 + 8];
        float4 u = *(const float4*)&As[row*GLD + (lane & 3)*32 + 12];
        float s = x.x*x.x+x.y*x.y+x.z*x.z+x.w*x.w + y.x*y.x+y.y*y.y+y.z*y.z+y.w*y.w
                + z.x*z.x+z.y*z.y+z.z*z.z+z.w*z.w + u.x*u.x+u.y*u.y+u.z*u.z+u.w*u.w;
        // reduce across 4 lanes, plus remaining 64 cols
        float4 x2 = *(const float4*)&As[row*GLD + 64 + (lane & 3)*16 + 0];
        float4 y2 = *(const float4*)&As[row*GLD + 64 + (lane & 3)*16 + 4];
        float4 z2 = *(const float4*)&As[row*GLD + 64 + (lane & 3)*16 + 8];
        float4 u2 = *(const float4*)&As[row*GLD + 64 + (lane & 3)*16 + 12];
        s += x2.x*x2.x+x2.y*x2.y+x2.z*x2.z+x2.w*x2.w + y2.x*y2.x+y2.y*y2.y+y2.z*y2.z+y2.w*y2.w
           + z2.x*z2.x+z2.y*z2.y+z2.z*z2.z+z2.w*z2.w + u2.x*u2.x+u2.y*u2.y+u2.z*u2.z+u2.w*u2.w;
        // oops: first group covered cols [ (lane&3)*32, +16 ), second [64 + (lane&3)*16, +16) — overlapping coverage is wrong.
        // Correct disjoint scheme below overrides s:
        s = 0.f;
        #pragma unroll
        for (int c = 0; c < 2; c++) {
            float4 a4 = *(const float4*)&As[row*GLD + (lane & 3)*16 + c*8 + ((c&1)?4:0)];
            (void)a4;
        }
        // simple exact version: 4 lanes x 32 cols each, float4 x 8
        s = 0.f;
        #pragma unroll
        for (int c = 0; c < 8; c++) {
            float4 a4 = *(const float4*)&As[row*GLD + (lane & 3)*32 + c*4];
            s += a4.x*a4.x + a4.y*a4.y + a4.z*a4.z + a4.w*a4.w;
        }
        s += __shfl_xor_sync(0xffffffffu, s, 1);
        s += __shfl_xor_sync(0xffffffffu, s, 2);
        if ((lane & 3) == 0) q2s[row] = s;
    }
    #pragma unroll
    for (int it = 0; it < 2; it++) {            // 128 B-rows: 8 warps x 2 its x 8 rows
        int row = warp*16 + it*8 + (lane >> 2);
        float s = 0.f;
        #pragma unroll
        for (int c = 0; c < 8; c++) {
            float4 a4 = *(const float4*)&Bs[row*GLD + (lane & 3)*32 + c*4];
            s += a4.x*a4.x + a4.y*a4.y + a4.z*a4.z + a4.w*a4.w;
        }
        s += __shfl_xor_sync(0xffffffffu, s, 1);
        s += __shfl_xor_sync(0xffffffffu, s, 2);
        if ((lane & 3) == 0) k2s[row] = s;
    }

    // mma: warp grid 4 (M) x 2 (N); warp tile 64x64
    int wm = warp & 3, wn = warp >> 2;
    wmma::fragment<wmma::accumulator, 16,16,8, float> acc[4][4];
    #pragma unroll
    for (int m = 0; m < 4; m++)
        #pragma unroll
        for (int n = 0; n < 4; n++) wmma::fill_fragment(acc[m][n], 0.f);
    #pragma unroll
    for (int k = 0; k < 128; k += 8) {
        wmma::fragment<wmma::matrix_a, 16,16,8, wmma::precision::tf32, wmma::row_major> af[4];
        wmma::fragment<wmma::matrix_b, 16,16,8, wmma::precision::tf32, wmma::col_major> bf[4];
        #pragma unroll
        for (int m = 0; m < 4; m++)
            wmma::load_matrix_sync(af[m], As + (wm*64 + m*16)*GLD + k, GLD);
        #pragma unroll
        for (int n = 0; n < 4; n++)
            wmma::load_matrix_sync(bf[n], Bs + (wn*64 + n*16)*GLD + k, GLD);
        #pragma unroll
        for (int m = 0; m < 4; m++)
            #pragma unroll
            for (int n = 0; n < 4; n++)
                wmma::mma_sync(acc[m][n], af[m], bf[n], acc[m][n]);
    }
    __syncthreads();
    #pragma unroll
    for (int m = 0; m < 4; m++)
        #pragma unroll
        for (int n = 0; n < 4; n++)
            wmma::store_matrix_sync(Cs + (wm*64 + m*16)*GLD + wn*64 + n*16, acc[m][n], GLD,
                                    wmma::mem_row_major);
    __syncthreads();

    // epilogue: s = 2c - q2 - k2, write raw to co, accumulate sum/sumsq
    float lsum = 0.f, lsq = 0.f;
    for (int t4 = tid; t4 < 256*32; t4 += 256) {
        int r = t4 >> 5, c4 = t4 & 31;
        float4 c = *(const float4*)&Cs[r*GLD + c4*4];
        float q2v = q2s[r];
        float4 s4;
        s4.x = 2.f*c.x - q2v - k2s[c4*4+0];
        s4.y = 2.f*c.y - q2v - k2s[c4*4+1];
        s4.z = 2.f*c.z - q2v - k2s[c4*4+2];
        s4.w = 2.f*c.w - q2v - k2s[c4*4+3];
        *(float4*)(co + ((size_t)(bh*Ln + bi0 + r))*Ln + bj0 + c4*4) = s4;
        lsum += s4.x + s4.y + s4.z + s4.w;
        lsq  += s4.x*s4.x + s4.y*s4.y + s4.z*s4.z + s4.w*s4.w;
    }
    double ds = (double)lsum, dq = (double)lsq;
    #pragma unroll
    for (int o = 16; o; o >>= 1) {
        ds += __shfl_xor_sync(0xffffffffu, ds, o);
        dq += __shfl_xor_sync(0xffffffffu, dq, o);
    }
    if (lane == 0) { rs[warp] = ds; rq[warp] = dq; }
    __syncthreads();
    if (warp == 0) {
        ds = (lane < 8) ? rs[lane] : 0.0;
        dq = (lane < 8) ? rq[lane] : 0.0;
        #pragma unroll
        for (int o = 4; o; o >>= 1) {
            ds += __shfl_xor_sync(0xffffffffu, ds, o);
            dq += __shfl_xor_sync(0xffffffffu, dq, o);
        }
        if (lane == 0) { atomicAdd(&g_sum1[h], ds); atomicAdd(&g_sumsq1[h], dq); }
    }
}

// ---------------- BN1 stats finalize ----------------
__global__ void stats1_kernel(const float* __restrict__ g1, const float* __restrict__ b1) {
    int h = threadIdx.x;
    if (h < Hn) {
        double n = (double)Bn*Ln*Ln;
        double m = g_sum1[h]/n;
        double var = g_sumsq1[h]/n - m*m;
        float rstd = (float)rsqrt(var + (double)EPSf);
        g_scale1[h] = g1[h]*rstd;
        g_shift1[h] = b1[h] - (float)m*rstd*g1[h];
    }
}

// ---------------- normalize + mask(0) + softmax (in place on co) + column sums ----------------
__global__ void __launch_bounds__(512) softmax_kernel(float* __restrict__ co) {
    __shared__ float colsum[Ln];
    __shared__ unsigned char sval[Ln];
    int bh = blockIdx.x >> 6;       // 64 row-blocks per (b,h)
    int rb = blockIdx.x & 63;
    int b = bh / Hn, h = bh % Hn;
    int tid = threadIdx.x, warp = tid >> 5, lane = tid & 31;
    for (int j = tid; j < Ln; j += 512) { colsum[j] = 0.f; sval[j] = g_valid[b*Ln + j]; }
    __syncthreads();

    int i = rb*16 + warp;
    bool rowvalid = sval[i] != 0;
    float scale = g_scale1[h], shift = g_shift1[h];
    float4* Sr = (float4*)(co + ((size_t)bh*Ln + i)*Ln);

    float v[32];
    float mx = -1e30f;
    #pragma unroll
    for (int c = 0; c < 8; c++) {
        float4 x = Sr[c*32 + lane];
        int j0 = c*128 + lane*4;
        float a0 = (rowvalid && sval[j0+0]) ? x.x*scale + shift : 0.f;
        float a1 = (rowvalid && sval[j0+1]) ? x.y*scale + shift : 0.f;
        float a2 = (rowvalid && sval[j0+2]) ? x.z*scale + shift : 0.f;
        float a3 = (rowvalid && sval[j0+3]) ? x.w*scale + shift : 0.f;
        v[c*4+0]=a0; v[c*4+1]=a1; v[c*4+2]=a2; v[c*4+3]=a3;
        mx = fmaxf(mx, fmaxf(fmaxf(a0,a1), fmaxf(a2,a3)));
    }
    #pragma unroll
    for (int o = 16; o; o >>= 1) mx = fmaxf(mx, __shfl_xor_sync(0xffffffffu, mx, o));
    float sum = 0.f;
    #pragma unroll
    for (int t = 0; t < 32; t++) { float e = __expf(v[t] - mx); v[t] = e; sum += e; }
    #pragma unroll
    for (int o = 16; o; o >>= 1) sum += __shfl_xor_sync(0xffffffffu, sum, o);
    float inv = 1.0f / sum;

    #pragma unroll
    for (int c = 0; c < 8; c++) {
        int j0 = c*128 + lane*4;
        float4 o4;
        o4.x = v[c*4+0]*inv; o4.y = v[c*4+1]*inv; o4.z = v[c*4+2]*inv; o4.w = v[c*4+3]*inv;
        Sr[c*32 + lane] = o4;
        atomicAdd(&colsum[j0+0], o4.x);
        atomicAdd(&colsum[j0+1], o4.y);
        atomicAdd(&colsum[j0+2], o4.z);
        atomicAdd(&colsum[j0+3], o4.w);
    }
    __syncthreads();
    for (int j = tid; j < Ln; j += 512) atomicAdd(&g_w[bh*Ln + j], colsum[j]);
}

// ---------------- BN2 stats (per head over B*L) ----------------
__global__ void stats2_kernel(const float* __restrict__ g2, const float* __restrict__ b2) {
    int h = blockIdx.x;
    int tid = threadIdx.x;
    float ls = 0.f, lq = 0.f;
    for (int b = 0; b < Bn; b++) {
        const float* wp = g_w + (b*Hn + h)*Ln;
        for (int j = tid; j < Ln; j += 256) { float x = wp[j]; ls += x; lq += x*x; }
    }
    double ds = (double)ls, dq = (double)lq;
    #pragma unroll
    for (int o = 16; o; o >>= 1) {
        ds += __shfl_xor_sync(0xffffffffu, ds, o);
        dq += __shfl_xor_sync(0xffffffffu, dq, o);
    }
    __shared__ double rs[8], rq[8];
    int warp = tid >> 5, lane = tid & 31;
    if (lane == 0) { rs[warp] = ds; rq[warp] = dq; }
    __syncthreads();
    if (tid == 0) {
        double S = 0.0, Q2 = 0.0;
        for (int wgi = 0; wgi < 8; wgi++) { S += rs[wgi]; Q2 += rq[wgi]; }
        double n = (double)Bn*Ln;
        double m = S/n;
        double var = Q2/n - m*m;
        float rstd = (float)rsqrt(var + (double)EPSf);
        g_scale2[h] = g2[h]*rstd;
        g_shift2[h] = b2[h] - (float)m*rstd*g2[h];
    }
}

// ---------------- posterior gate ----------------
__global__ void gate_kernel(const float* __restrict__ Wp, const float* __restrict__ bp) {
    int idx = blockIdx.x*blockDim.x + threadIdx.x;
    if (idx >= Bn*Ln) return;
    int b = idx >> 10, l = idx & (Ln-1);
    float z0 = bp[0], z1 = bp[1];
    #pragma unroll
    for (int h = 0; h < Hn; h++) {
        float wn = g_w[(b*Hn + h)*Ln + l]*g_scale2[h] + g_shift2[h];
        z0 += Wp[h]      * wn;
        z1 += Wp[Hn + h] * wn;
    }
    float d = z1 - z0;
    g_p[idx] = 1.f/(1.f + __expf(d));
}

// ---------------- final masked softmax over L per batch ----------------
__global__ void final_kernel(float* __restrict__ out) {
    int b = blockIdx.x, l = threadIdx.x;
    __shared__ float redm[32], redsum[32], bc[2];
    const float NEG_INF = __int_as_float(0xff800000);
    float x = g_valid[b*Ln + l] ? g_p[b*Ln + l] : NEG_INF;
    int warp = l >> 5, lane = l & 31;
    float m = x;
    #pragma unroll
    for (int o = 16; o; o >>= 1) m = fmaxf(m, __shfl_xor_sync(0xffffffffu, m, o));
    if (lane == 0) redm[warp] = m;
    __syncthreads();
    if (warp == 0) {
        m = redm[lane];
        #pragma unroll
        for (int o = 16; o; o >>= 1) m = fmaxf(m, __shfl_xor_sync(0xffffffffu, m, o));
        if (lane == 0) bc[0] = m;
    }
    __syncthreads();
    m = bc[0];
    float e = __expf(x - m);
    float s = e;
    #pragma unroll
    for (int o = 16; o; o >>= 1) s += __shfl_xor_sync(0xffffffffu, s, o);
    if (lane == 0) redsum[warp] = s;
    __syncthreads();
    if (warp == 0) {
        s = redsum[lane];
        #pragma unroll
        for (int o = 16; o; o >>= 1) s += __shfl_xor_sync(0xffffffffu, s, o);
        if (lane == 0) bc[1] = s;
    }
    __syncthreads();
    out[OFF_W + b*Ln + l] = e / bc[1];
}

// ---------------- launch ----------------
extern "C" void kernel_launch(void* const* d_in, const int* in_sizes, int n_in,
                              void* d_out, int out_size) {
    const float* Q  = (const float*)d_in[0];
    const float* K  = (const float*)d_in[1];
    const float* V  = (const float*)d_in[2];
    const unsigned int* bx = (const unsigned int*)d_in[4];
    const float* g1 = (const float*)d_in[5];
    const float* b1 = (const float*)d_in[6];
    const float* g2 = (const float*)d_in[7];
    const float* b2 = (const float*)d_in[8];
    const float* Wp = (const float*)d_in[9];
    const float* bp = (const float*)d_in[10];
    float* out = (float*)d_out;

    const int SMG = (256 + 128)*GLD*4;   // 202752
    cudaFuncSetAttribute(gemm_kernel, cudaFuncAttributeMaxDynamicSharedMemorySize, SMG);

    zero_kernel<<<(BHn*Ln + 255)/256, 256>>>();
    mask_kernel<<<1, 256>>>(bx);
    vout_kernel<<<(BHn*Ln*DHn/4 + 255)/256, 256>>>(V, out);
    gemm_kernel<<<dim3(Ln/128, Ln/256, BHn), 256, SMG>>>(Q, K, out);
    stats1_kernel<<<1, 32>>>(g1, b1);
    softmax_kernel<<<BHn*(Ln/16), 512>>>(out);
    stats2_kernel<<<Hn, 256>>>(g2, b2);
    gate_kernel<<<(Bn*Ln + 255)/256, 256>>>(Wp, bp);
    final_kernel<<<Bn, Ln>>>(out);
}